// round 9
// baseline (speedup 1.0000x reference)
#include <cuda_runtime.h>
#include <cuda_fp16.h>
#include <cstdint>

#define HID     128
#define M_TILE  128
#define THREADS 256
#define LDHX    152     // xh stride (halves): 304B rows -> conflict-free ldmatrix
#define LDW     136     // weight stride (halves): 272B rows -> conflict-free
#define K1      144     // GEMM1 K: 128 feats + agg + ones + 14 zero pad (9 ksteps)

// Device globals (no cudaMalloc allowed). Zero-initialized at module load.
__device__ __half g_hh[65536 * 128];   // fp16 copy of h (rows >= n_nodes stay 0)
__device__ float  g_agg[65536];        // re-zeroed by mlp after read each replay

__device__ __forceinline__ float silu(float x) {
    return x * (1.0f / (1.0f + __expf(-x)));
}
__device__ __forceinline__ uint32_t smem_u32(const void* p) {
    return (uint32_t)__cvta_generic_to_shared(p);
}
__device__ __forceinline__ void ldsm4(uint32_t& r0, uint32_t& r1, uint32_t& r2,
                                      uint32_t& r3, uint32_t a) {
    asm volatile("ldmatrix.sync.aligned.m8n8.x4.shared.b16 {%0,%1,%2,%3}, [%4];"
                 : "=r"(r0), "=r"(r1), "=r"(r2), "=r"(r3) : "r"(a));
}
__device__ __forceinline__ void ldsm4t(uint32_t& r0, uint32_t& r1, uint32_t& r2,
                                       uint32_t& r3, uint32_t a) {
    asm volatile("ldmatrix.sync.aligned.m8n8.x4.trans.shared.b16 {%0,%1,%2,%3}, [%4];"
                 : "=r"(r0), "=r"(r1), "=r"(r2), "=r"(r3) : "r"(a));
}
__device__ __forceinline__ void mma16816(float4& d, uint32_t a0, uint32_t a1,
                                         uint32_t a2, uint32_t a3,
                                         uint32_t b0, uint32_t b1) {
    asm volatile(
        "mma.sync.aligned.m16n8k16.row.col.f32.f16.f16.f32 "
        "{%0,%1,%2,%3}, {%4,%5,%6,%7}, {%8,%9}, {%0,%1,%2,%3};"
        : "+f"(d.x), "+f"(d.y), "+f"(d.z), "+f"(d.w)
        : "r"(a0), "r"(a1), "r"(a2), "r"(a3), "r"(b0), "r"(b1));
}
__device__ __forceinline__ void cp16(uint32_t dst, const void* src) {
    asm volatile("cp.async.cg.shared.global [%0], [%1], 16;" :: "r"(dst), "l"(src));
}
__device__ __forceinline__ void cp_commit() {
    asm volatile("cp.async.commit_group;" ::: "memory");
}
__device__ __forceinline__ void cp_wait1() {
    asm volatile("cp.async.wait_group 1;" ::: "memory");
}
__device__ __forceinline__ uint32_t packh2(float a, float b) {
    __half2 h = __floats2half2_rn(a, b);
    return *reinterpret_cast<uint32_t*>(&h);
}

// ---------------------------------------------------------------------------
// prep: (a) convert h -> g_hh fp16, (b) scatter-add distances into g_agg.
// Edge dtype probed (jax randint int64 demotes to int32 when x64 off).
// ---------------------------------------------------------------------------
__global__ void prep_kernel(const float* __restrict__ h,
                            const int* __restrict__ edges_i32,
                            const float* __restrict__ dist,
                            int n_nodes, int E) {
    __shared__ int sstride;
    if (threadIdx.x == 0) {
        bool all_zero = true;
        int probe = E < 16 ? E : 16;
        for (int j = 0; j < probe; j++)
            if (edges_i32[2 * j + 1] != 0) { all_zero = false; break; }
        sstride = all_zero ? 2 : 1;
    }
    __syncthreads();
    int stride = sstride;
    int gid = blockIdx.x * blockDim.x + threadIdx.x;
    int conv_n = n_nodes * 32;            // float4 units
    int scat_n = (E + 3) >> 2;
    int total = conv_n > scat_n ? conv_n : scat_n;
    for (int i = gid; i < total; i += gridDim.x * blockDim.x) {
        if (i < conv_n) {
            float4 v = __ldg((const float4*)&h[(size_t)i * 4]);
            uint2 pk;
            pk.x = packh2(v.x, v.y);
            pk.y = packh2(v.z, v.w);
            *reinterpret_cast<uint2*>(&g_hh[(size_t)i * 4]) = pk;
        }
        if (i < scat_n) {
            int i4 = i * 4;
            if (i4 + 3 < E) {
                float4 d = __ldg((const float4*)&dist[i4]);
                int r0, r1, r2, r3;
                if (stride == 1) {
                    int4 r = __ldg((const int4*)&edges_i32[i4]);
                    r0 = r.x; r1 = r.y; r2 = r.z; r3 = r.w;
                } else {
                    int4 ra = __ldg((const int4*)&edges_i32[2 * i4]);
                    int4 rb = __ldg((const int4*)&edges_i32[2 * i4 + 4]);
                    r0 = ra.x; r1 = ra.z; r2 = rb.x; r3 = rb.z;
                }
                atomicAdd(&g_agg[r0], d.x);
                atomicAdd(&g_agg[r1], d.y);
                atomicAdd(&g_agg[r2], d.z);
                atomicAdd(&g_agg[r3], d.w);
            } else {
                for (int j = i4; j < E; j++)
                    atomicAdd(&g_agg[edges_i32[(long long)j * stride]], dist[j]);
            }
        }
    }
}

// ---------------------------------------------------------------------------
// smem: w1h[144][LDW] | w2h[128][LDW] | xh0[128][LDHX] | xh1[128][LDHX]
// ---------------------------------------------------------------------------
#define SM_W1   0
#define SM_W2   (K1 * LDW * 2)                    // 39168
#define SM_X0   (SM_W2 + 128 * LDW * 2)           // 73984
#define SM_X1   (SM_X0 + 128 * LDHX * 2)          // 112896
#define SM_TOT  (SM_X1 + 128 * LDHX * 2)          // 151808

__global__ void __launch_bounds__(THREADS, 1)
mlp_kernel(const float* __restrict__ W1, const float* __restrict__ b1,
           const float* __restrict__ W2, const float* __restrict__ b2,
           float* __restrict__ out, int n_nodes, int n_tiles)
{
    extern __shared__ char sm[];
    __half* w1h = (__half*)(sm + SM_W1);
    __half* w2h = (__half*)(sm + SM_W2);
    __half* xb[2] = { (__half*)(sm + SM_X0), (__half*)(sm + SM_X1) };

    const int tid  = threadIdx.x;
    const int l    = tid & 31;
    const int warp = tid >> 5;
    const int r0w  = warp * 16;          // warp owns rows r0w..r0w+15, all 128 cols

    // ---- stage extended weights (fp16) ----
    for (int idx = tid; idx < K1 * 32; idx += THREADS) {
        int k = idx >> 5, c4 = (idx & 31) << 2;
        float4 v1 = make_float4(0.f, 0.f, 0.f, 0.f);
        if (k < 128)      v1 = __ldg((const float4*)&W1[k * HID + c4]);
        else if (k == 128) v1 = __ldg((const float4*)&W1[128 * HID + c4]); // agg row
        else if (k == 129) v1 = __ldg((const float4*)&b1[c4]);             // b1 row
        uint2 pk;
        pk.x = packh2(v1.x, v1.y);
        pk.y = packh2(v1.z, v1.w);
        *reinterpret_cast<uint2*>(&w1h[(size_t)k * LDW + c4]) = pk;
        if (k < 128) {
            float4 v2 = __ldg((const float4*)&W2[k * HID + c4]);
            uint2 qk;
            qk.x = packh2(v2.x, v2.y);
            qk.y = packh2(v2.z, v2.w);
            *reinterpret_cast<uint2*>(&w2h[(size_t)k * LDW + c4]) = qk;
        }
    }
    // constant X columns 129..143 (ones + zero pad), both buffers, once
    if (tid < 128) {
        for (int bfi = 0; bfi < 2; bfi++) {
            xb[bfi][(size_t)tid * LDHX + 129] = __float2half(1.0f);
#pragma unroll
            for (int c = 130; c < K1; c++)
                xb[bfi][(size_t)tid * LDHX + c] = __float2half(0.0f);
        }
    }

    // ---- lane-invariant ldmatrix addresses ----
    const int g  = l >> 3, i8 = l & 7;
    const uint32_t aoff =
        (uint32_t)((r0w + ((g & 1) << 3) + i8) * LDHX + ((g >> 1) << 3)) * 2;
    const uint32_t boff =
        (uint32_t)((((g & 1) << 3) + i8) * LDW + ((g >> 1) << 3)) * 2;
    const uint32_t w1b = smem_u32(w1h) + boff;
    const uint32_t w2b = smem_u32(w2h) + boff;
    const uint32_t xbs[2] = { smem_u32(xb[0]), smem_u32(xb[1]) };
    const uint32_t DK = 16 * LDW * 2;    // B k-step byte advance

    // b2 column pairs for this lane (fixed across tiles)
    float2 b2r[16];
#pragma unroll
    for (int t = 0; t < 16; t++) {
        int c = t * 8 + ((l & 3) << 1);
        b2r[t] = make_float2(__ldg(&b2[c]), __ldg(&b2[c + 1]));
    }

    // ---- prologue: fill tile0 into buffer 0 ----
    if (blockIdx.x < n_tiles) {
        int base = blockIdx.x * M_TILE;
#pragma unroll
        for (int t = 0; t < 8; t++) {
            int idx = tid + t * THREADS;
            int m = idx >> 4, s = (idx & 15) << 3;
            cp16(xbs[0] + (uint32_t)(m * LDHX + s) * 2,
                 &g_hh[(size_t)(base + m) * HID + s]);
        }
    }
    cp_commit();

    int it = 0;
    for (int tile = blockIdx.x; tile < n_tiles; tile += gridDim.x, it++) {
        const int base = tile * M_TILE;
        const int cur = it & 1;
        const __half* xc = xb[cur];
        const uint32_t xcb = xbs[cur];

        __syncthreads();   // S1: prev tile fully consumed (other buffer free)

        // issue next tile's fill into the other buffer (or an empty group)
        int nt = tile + gridDim.x;
        if (nt < n_tiles) {
            int nb = nt * M_TILE;
#pragma unroll
            for (int t = 0; t < 8; t++) {
                int idx = tid + t * THREADS;
                int m = idx >> 4, s = (idx & 15) << 3;
                cp16(xbs[cur ^ 1] + (uint32_t)(m * LDHX + s) * 2,
                     &g_hh[(size_t)(nb + m) * HID + s]);
            }
        }
        cp_commit();
        cp_wait1();        // current buffer's fill complete

        // agg column (col 128) + re-zero g_agg
        if (tid < 128) {
            int gn = base + tid;
            float a = 0.f;
            if (gn < n_nodes) { a = g_agg[gn] * 0.01f; g_agg[gn] = 0.f; }
            ((__half*)xc)[(size_t)tid * LDHX + 128] = __float2half(a);
        }
        __syncthreads();   // S2: fill + agg visible

        // ---- GEMM1: acc[t] (n8-tile t) = Xext[r0w:+16, 0:144] @ W1ext ----
        float4 acc[16];
#pragma unroll
        for (int t = 0; t < 16; t++) acc[t] = make_float4(0.f, 0.f, 0.f, 0.f);
#pragma unroll
        for (int ks = 0; ks < 9; ks++) {
            uint32_t a0, a1, a2, a3;
            ldsm4(a0, a1, a2, a3, xcb + aoff + ks * 32);
#pragma unroll
            for (int p = 0; p < 8; p++) {
                uint32_t b0, b1_, b2_, b3;
                ldsm4t(b0, b1_, b2_, b3, w1b + p * 32 + ks * DK);
                mma16816(acc[2 * p],     a0, a1, a2, a3, b0, b1_);
                mma16816(acc[2 * p + 1], a0, a1, a2, a3, b2_, b3);
            }
        }

        // ---- epilogue in registers: T = silu(D1), repacked as A-fragments ----
        uint32_t au[8][4];
#pragma unroll
        for (int ks = 0; ks < 8; ks++) {
            const float4& e = acc[2 * ks];
            const float4& o = acc[2 * ks + 1];
            au[ks][0] = packh2(silu(e.x), silu(e.y));
            au[ks][1] = packh2(silu(e.z), silu(e.w));
            au[ks][2] = packh2(silu(o.x), silu(o.y));
            au[ks][3] = packh2(silu(o.z), silu(o.w));
        }

        // ---- GEMM2: acc2 = T @ W2 (A from registers, no smem round-trip) ----
        float4 acc2[16];
#pragma unroll
        for (int t = 0; t < 16; t++) acc2[t] = make_float4(0.f, 0.f, 0.f, 0.f);
#pragma unroll
        for (int ks = 0; ks < 8; ks++) {
#pragma unroll
            for (int p = 0; p < 8; p++) {
                uint32_t b0, b1_, b2_, b3;
                ldsm4t(b0, b1_, b2_, b3, w2b + p * 32 + ks * DK);
                mma16816(acc2[2 * p],     au[ks][0], au[ks][1], au[ks][2], au[ks][3], b0, b1_);
                mma16816(acc2[2 * p + 1], au[ks][0], au[ks][1], au[ks][2], au[ks][3], b2_, b3);
            }
        }

        // ---- store: out = h(residual, fp16 from xc) + acc2 + b2 ----
        const int rr = r0w + (l >> 2);
        const int gn0 = base + rr, gn1 = gn0 + 8;
#pragma unroll
        for (int t = 0; t < 16; t++) {
            int c = t * 8 + ((l & 3) << 1);
            if (gn0 < n_nodes) {
                __half2 hv = *(const __half2*)&xc[(size_t)rr * LDHX + c];
                float2 o = make_float2(acc2[t].x + __low2float(hv) + b2r[t].x,
                                       acc2[t].y + __high2float(hv) + b2r[t].y);
                *(float2*)&out[(size_t)gn0 * HID + c] = o;
            }
            if (gn1 < n_nodes) {
                __half2 hv = *(const __half2*)&xc[(size_t)(rr + 8) * LDHX + c];
                float2 o = make_float2(acc2[t].z + __low2float(hv) + b2r[t].x,
                                       acc2[t].w + __high2float(hv) + b2r[t].y);
                *(float2*)&out[(size_t)gn1 * HID + c] = o;
            }
        }
    }
}

// ---------------------------------------------------------------------------
extern "C" void kernel_launch(void* const* d_in, const int* in_sizes, int n_in,
                              void* d_out, int out_size) {
    const float* h    = (const float*)d_in[0];
    const int*   edg  = (const int*)  d_in[1];
    const float* dist = (const float*)d_in[2];
    const float* W1   = (const float*)d_in[9];   // W_n1 [129,128]
    const float* b1   = (const float*)d_in[10];
    const float* W2   = (const float*)d_in[11];  // W_n2 [128,128]
    const float* b2   = (const float*)d_in[12];
    float* out = (float*)d_out;

    int n_nodes = in_sizes[0] / HID;
    int E       = in_sizes[2];

    int conv_n = n_nodes * 32;
    int scat_n = (E + 3) / 4;
    int total  = conv_n > scat_n ? conv_n : scat_n;
    prep_kernel<<<(total + 255) / 256, 256>>>(h, edg, dist, n_nodes, E);

    cudaFuncSetAttribute(mlp_kernel,
                         cudaFuncAttributeMaxDynamicSharedMemorySize, SM_TOT);
    int sms = 148;
    cudaDeviceGetAttribute(&sms, cudaDevAttrMultiProcessorCount, 0);
    int n_tiles = (n_nodes + M_TILE - 1) / M_TILE;
    int grid = n_tiles < sms ? n_tiles : sms;
    mlp_kernel<<<grid, THREADS, SM_TOT>>>(W1, b1, W2, b2, out, n_nodes, n_tiles);
}

// round 10
// speedup vs baseline: 1.0257x; 1.0257x over previous
#include <cuda_runtime.h>
#include <cuda_fp16.h>
#include <cstdint>

#define HID     128
#define M_TILE  128
#define THREADS 256
#define LDHX    152     // xh stride (halves): 304B rows -> conflict-free ldmatrix
#define LDW     136     // weight stride (halves): 272B rows -> conflict-free
#define K1      144     // GEMM1 K: 128 feats + agg + ones + 14 zero pad (9 ksteps)

// Device globals (no cudaMalloc allowed). Zero-initialized at module load.
__device__ __half g_hh[65536 * 128];   // fp16 copy of h (rows >= n_nodes stay 0)
__device__ float  g_agg[65536];        // re-zeroed by mlp after read each replay

__device__ __forceinline__ float silu(float x) {
    return x * (1.0f / (1.0f + __expf(-x)));
}
__device__ __forceinline__ uint32_t smem_u32(const void* p) {
    return (uint32_t)__cvta_generic_to_shared(p);
}
__device__ __forceinline__ void ldsm4(uint32_t* r, uint32_t a) {
    asm volatile("ldmatrix.sync.aligned.m8n8.x4.shared.b16 {%0,%1,%2,%3}, [%4];"
                 : "=r"(r[0]), "=r"(r[1]), "=r"(r[2]), "=r"(r[3]) : "r"(a));
}
__device__ __forceinline__ void ldsm4t(uint32_t* r, uint32_t a) {
    asm volatile("ldmatrix.sync.aligned.m8n8.x4.trans.shared.b16 {%0,%1,%2,%3}, [%4];"
                 : "=r"(r[0]), "=r"(r[1]), "=r"(r[2]), "=r"(r[3]) : "r"(a));
}
__device__ __forceinline__ void mma16816(float4& d, const uint32_t* a,
                                         uint32_t b0, uint32_t b1) {
    asm volatile(
        "mma.sync.aligned.m16n8k16.row.col.f32.f16.f16.f32 "
        "{%0,%1,%2,%3}, {%4,%5,%6,%7}, {%8,%9}, {%0,%1,%2,%3};"
        : "+f"(d.x), "+f"(d.y), "+f"(d.z), "+f"(d.w)
        : "r"(a[0]), "r"(a[1]), "r"(a[2]), "r"(a[3]), "r"(b0), "r"(b1));
}
__device__ __forceinline__ void cp16(uint32_t dst, const void* src) {
    asm volatile("cp.async.cg.shared.global [%0], [%1], 16;" :: "r"(dst), "l"(src));
}
__device__ __forceinline__ void cp_commit() {
    asm volatile("cp.async.commit_group;" ::: "memory");
}
__device__ __forceinline__ void cp_wait1() {
    asm volatile("cp.async.wait_group 1;" ::: "memory");
}
__device__ __forceinline__ uint32_t packh2(float a, float b) {
    __half2 h = __floats2half2_rn(a, b);
    return *reinterpret_cast<uint32_t*>(&h);
}

// ---------------------------------------------------------------------------
// prep: (a) convert h -> g_hh fp16, (b) scatter-add distances into g_agg.
// Edge dtype probed (jax randint int64 demotes to int32 when x64 off).
// ---------------------------------------------------------------------------
__global__ void prep_kernel(const float* __restrict__ h,
                            const int* __restrict__ edges_i32,
                            const float* __restrict__ dist,
                            int n_nodes, int E) {
    __shared__ int sstride;
    if (threadIdx.x == 0) {
        bool all_zero = true;
        int probe = E < 16 ? E : 16;
        for (int j = 0; j < probe; j++)
            if (edges_i32[2 * j + 1] != 0) { all_zero = false; break; }
        sstride = all_zero ? 2 : 1;
    }
    __syncthreads();
    int stride = sstride;
    int gid = blockIdx.x * blockDim.x + threadIdx.x;
    int conv_n = n_nodes * 32;            // float4 units
    int scat_n = (E + 3) >> 2;
    int total = conv_n > scat_n ? conv_n : scat_n;
    for (int i = gid; i < total; i += gridDim.x * blockDim.x) {
        if (i < conv_n) {
            float4 v = __ldg((const float4*)&h[(size_t)i * 4]);
            uint2 pk;
            pk.x = packh2(v.x, v.y);
            pk.y = packh2(v.z, v.w);
            *reinterpret_cast<uint2*>(&g_hh[(size_t)i * 4]) = pk;
        }
        if (i < scat_n) {
            int i4 = i * 4;
            if (i4 + 3 < E) {
                float4 d = __ldg((const float4*)&dist[i4]);
                int r0, r1, r2, r3;
                if (stride == 1) {
                    int4 r = __ldg((const int4*)&edges_i32[i4]);
                    r0 = r.x; r1 = r.y; r2 = r.z; r3 = r.w;
                } else {
                    int4 ra = __ldg((const int4*)&edges_i32[2 * i4]);
                    int4 rb = __ldg((const int4*)&edges_i32[2 * i4 + 4]);
                    r0 = ra.x; r1 = ra.z; r2 = rb.x; r3 = rb.z;
                }
                atomicAdd(&g_agg[r0], d.x);
                atomicAdd(&g_agg[r1], d.y);
                atomicAdd(&g_agg[r2], d.z);
                atomicAdd(&g_agg[r3], d.w);
            } else {
                for (int j = i4; j < E; j++)
                    atomicAdd(&g_agg[edges_i32[(long long)j * stride]], dist[j]);
            }
        }
    }
}

// ---------------------------------------------------------------------------
// smem: w1h[144][LDW] | w2h[128][LDW] | xh0[128][LDHX] | xh1[128][LDHX]
// ---------------------------------------------------------------------------
#define SM_W1   0
#define SM_W2   (K1 * LDW * 2)                    // 39168
#define SM_X0   (SM_W2 + 128 * LDW * 2)           // 73984
#define SM_X1   (SM_X0 + 128 * LDHX * 2)          // 112896
#define SM_TOT  (SM_X1 + 128 * LDHX * 2)          // 151808

__global__ void __launch_bounds__(THREADS, 1)
mlp_kernel(const float* __restrict__ W1, const float* __restrict__ b1,
           const float* __restrict__ W2, const float* __restrict__ b2,
           float* __restrict__ out, int n_nodes, int n_tiles)
{
    extern __shared__ char sm[];
    __half* w1h = (__half*)(sm + SM_W1);
    __half* w2h = (__half*)(sm + SM_W2);
    __half* xb[2] = { (__half*)(sm + SM_X0), (__half*)(sm + SM_X1) };

    const int tid  = threadIdx.x;
    const int l    = tid & 31;
    const int warp = tid >> 5;
    const int r0w  = warp * 16;          // warp owns rows r0w..r0w+15, all 128 cols

    // ---- stage extended weights (fp16) ----
    for (int idx = tid; idx < K1 * 32; idx += THREADS) {
        int k = idx >> 5, c4 = (idx & 31) << 2;
        float4 v1 = make_float4(0.f, 0.f, 0.f, 0.f);
        if (k < 128)      v1 = __ldg((const float4*)&W1[k * HID + c4]);
        else if (k == 128) v1 = __ldg((const float4*)&W1[128 * HID + c4]); // agg row
        else if (k == 129) v1 = __ldg((const float4*)&b1[c4]);             // b1 row
        uint2 pk;
        pk.x = packh2(v1.x, v1.y);
        pk.y = packh2(v1.z, v1.w);
        *reinterpret_cast<uint2*>(&w1h[(size_t)k * LDW + c4]) = pk;
        if (k < 128) {
            float4 v2 = __ldg((const float4*)&W2[k * HID + c4]);
            uint2 qk;
            qk.x = packh2(v2.x, v2.y);
            qk.y = packh2(v2.z, v2.w);
            *reinterpret_cast<uint2*>(&w2h[(size_t)k * LDW + c4]) = qk;
        }
    }
    // constant X columns 129..143 (ones + zero pad), both buffers, once
    if (tid < 128) {
        for (int bfi = 0; bfi < 2; bfi++) {
            xb[bfi][(size_t)tid * LDHX + 129] = __float2half(1.0f);
#pragma unroll
            for (int c = 130; c < K1; c++)
                xb[bfi][(size_t)tid * LDHX + c] = __float2half(0.0f);
        }
    }

    // ---- lane-invariant ldmatrix addresses ----
    const int g  = l >> 3, i8 = l & 7;
    const uint32_t aoff =
        (uint32_t)((r0w + ((g & 1) << 3) + i8) * LDHX + ((g >> 1) << 3)) * 2;
    const uint32_t boff =
        (uint32_t)((((g & 1) << 3) + i8) * LDW + ((g >> 1) << 3)) * 2;
    const uint32_t w1b = smem_u32(w1h) + boff;
    const uint32_t w2b = smem_u32(w2h) + boff;
    const uint32_t xbs[2] = { smem_u32(xb[0]), smem_u32(xb[1]) };
    const uint32_t DK = 16 * LDW * 2;    // B k-step byte advance

    // b2 column pairs for this lane (fixed across tiles)
    float2 b2r[16];
#pragma unroll
    for (int t = 0; t < 16; t++) {
        int c = t * 8 + ((l & 3) << 1);
        b2r[t] = make_float2(__ldg(&b2[c]), __ldg(&b2[c + 1]));
    }

    // ---- prologue: fill tile0 into buffer 0 ----
    if (blockIdx.x < n_tiles) {
        int base = blockIdx.x * M_TILE;
#pragma unroll
        for (int t = 0; t < 8; t++) {
            int idx = tid + t * THREADS;
            int m = idx >> 4, s = (idx & 15) << 3;
            cp16(xbs[0] + (uint32_t)(m * LDHX + s) * 2,
                 &g_hh[(size_t)(base + m) * HID + s]);
        }
    }
    cp_commit();

    int it = 0;
    for (int tile = blockIdx.x; tile < n_tiles; tile += gridDim.x, it++) {
        const int base = tile * M_TILE;
        const int cur = it & 1;
        const __half* xc = xb[cur];
        const uint32_t xcb = xbs[cur];

        __syncthreads();   // S1: prev tile fully consumed (other buffer free)

        // issue next tile's fill into the other buffer
        int nt = tile + gridDim.x;
        if (nt < n_tiles) {
            int nb = nt * M_TILE;
#pragma unroll
            for (int t = 0; t < 8; t++) {
                int idx = tid + t * THREADS;
                int m = idx >> 4, s = (idx & 15) << 3;
                cp16(xbs[cur ^ 1] + (uint32_t)(m * LDHX + s) * 2,
                     &g_hh[(size_t)(nb + m) * HID + s]);
            }
        }
        cp_commit();
        cp_wait1();        // current buffer's fill complete

        // agg column (col 128) + re-zero g_agg
        if (tid < 128) {
            int gn = base + tid;
            float a = 0.f;
            if (gn < n_nodes) { a = g_agg[gn] * 0.01f; g_agg[gn] = 0.f; }
            ((__half*)xc)[(size_t)tid * LDHX + 128] = __float2half(a);
        }
        __syncthreads();   // S2: fill + agg visible

        // ================= GEMM1 (K=144, 9 ksteps), pipelined =================
        float4 acc[16];
#pragma unroll
        for (int t = 0; t < 16; t++) acc[t] = make_float4(0.f, 0.f, 0.f, 0.f);

        uint32_t Af[2][4], Bf[2][8][4];
        ldsm4(Af[0], xcb + aoff);
#pragma unroll
        for (int p = 0; p < 8; p++) ldsm4t(Bf[0][p], w1b + p * 32);

#pragma unroll
        for (int ks = 0; ks < 9; ks++) {
            const int cu = ks & 1, nx = cu ^ 1;
            if (ks < 8) {   // prefetch next k-step's fragments FIRST
                ldsm4(Af[nx], xcb + aoff + (ks + 1) * 32);
#pragma unroll
                for (int p = 0; p < 8; p++)
                    ldsm4t(Bf[nx][p], w1b + p * 32 + (ks + 1) * DK);
            }
#pragma unroll
            for (int p = 0; p < 8; p++) {   // consume resident fragments
                mma16816(acc[2 * p],     Af[cu], Bf[cu][p][0], Bf[cu][p][1]);
                mma16816(acc[2 * p + 1], Af[cu], Bf[cu][p][2], Bf[cu][p][3]);
            }
        }

        // ---- epilogue in registers: T = silu(D1), repacked as A-fragments ----
        uint32_t au[8][4];
#pragma unroll
        for (int ks = 0; ks < 8; ks++) {
            const float4& e = acc[2 * ks];
            const float4& o = acc[2 * ks + 1];
            au[ks][0] = packh2(silu(e.x), silu(e.y));
            au[ks][1] = packh2(silu(e.z), silu(e.w));
            au[ks][2] = packh2(silu(o.x), silu(o.y));
            au[ks][3] = packh2(silu(o.z), silu(o.w));
        }

        // ================= GEMM2 (K=128, 8 ksteps), pipelined B ===============
        float4 acc2[16];
#pragma unroll
        for (int t = 0; t < 16; t++) acc2[t] = make_float4(0.f, 0.f, 0.f, 0.f);

        uint32_t Bg[2][8][4];
#pragma unroll
        for (int p = 0; p < 8; p++) ldsm4t(Bg[0][p], w2b + p * 32);

#pragma unroll
        for (int ks = 0; ks < 8; ks++) {
            const int cu = ks & 1, nx = cu ^ 1;
            if (ks < 7) {
#pragma unroll
                for (int p = 0; p < 8; p++)
                    ldsm4t(Bg[nx][p], w2b + p * 32 + (ks + 1) * DK);
            }
#pragma unroll
            for (int p = 0; p < 8; p++) {
                mma16816(acc2[2 * p],     au[ks], Bg[cu][p][0], Bg[cu][p][1]);
                mma16816(acc2[2 * p + 1], au[ks], Bg[cu][p][2], Bg[cu][p][3]);
            }
        }

        // ---- store: out = h(residual, fp16 from xc) + acc2 + b2 ----
        const int rr = r0w + (l >> 2);
        const int gn0 = base + rr, gn1 = gn0 + 8;
#pragma unroll
        for (int t = 0; t < 16; t++) {
            int c = t * 8 + ((l & 3) << 1);
            if (gn0 < n_nodes) {
                __half2 hv = *(const __half2*)&xc[(size_t)rr * LDHX + c];
                float2 o = make_float2(acc2[t].x + __low2float(hv) + b2r[t].x,
                                       acc2[t].y + __high2float(hv) + b2r[t].y);
                *(float2*)&out[(size_t)gn0 * HID + c] = o;
            }
            if (gn1 < n_nodes) {
                __half2 hv = *(const __half2*)&xc[(size_t)(rr + 8) * LDHX + c];
                float2 o = make_float2(acc2[t].z + __low2float(hv) + b2r[t].x,
                                       acc2[t].w + __high2float(hv) + b2r[t].y);
                *(float2*)&out[(size_t)gn1 * HID + c] = o;
            }
        }
    }
}

// ---------------------------------------------------------------------------
extern "C" void kernel_launch(void* const* d_in, const int* in_sizes, int n_in,
                              void* d_out, int out_size) {
    const float* h    = (const float*)d_in[0];
    const int*   edg  = (const int*)  d_in[1];
    const float* dist = (const float*)d_in[2];
    const float* W1   = (const float*)d_in[9];   // W_n1 [129,128]
    const float* b1   = (const float*)d_in[10];
    const float* W2   = (const float*)d_in[11];  // W_n2 [128,128]
    const float* b2   = (const float*)d_in[12];
    float* out = (float*)d_out;

    int n_nodes = in_sizes[0] / HID;
    int E       = in_sizes[2];

    int conv_n = n_nodes * 32;
    int scat_n = (E + 3) / 4;
    int total  = conv_n > scat_n ? conv_n : scat_n;
    prep_kernel<<<(total + 255) / 256, 256>>>(h, edg, dist, n_nodes, E);

    cudaFuncSetAttribute(mlp_kernel,
                         cudaFuncAttributeMaxDynamicSharedMemorySize, SM_TOT);
    int sms = 148;
    cudaDeviceGetAttribute(&sms, cudaDevAttrMultiProcessorCount, 0);
    int n_tiles = (n_nodes + M_TILE - 1) / M_TILE;
    int grid = n_tiles < sms ? n_tiles : sms;
    mlp_kernel<<<grid, THREADS, SM_TOT>>>(W1, b1, W2, b2, out, n_nodes, n_tiles);
}

// round 11
// speedup vs baseline: 1.0321x; 1.0063x over previous
#include <cuda_runtime.h>
#include <cuda_fp16.h>
#include <mma.h>
#include <cstdint>

using namespace nvcuda;

#define HID     128
#define M_TILE  128
#define THREADS 512
#define LDH     136     // half stride: 272B rows -> conflict-free LDSM

// Device globals (no cudaMalloc). Zero-initialized at module load.
__device__ __half g_hh[65536 * 128];   // fp16 copy of h (rows >= n_nodes stay 0)
__device__ float  g_agg[65536];        // re-zeroed by mlp after read each replay

__device__ __forceinline__ float silu(float x) {
    return x * (1.0f / (1.0f + __expf(-x)));
}
__device__ __forceinline__ uint32_t packh2(float a, float b) {
    __half2 h = __floats2half2_rn(a, b);
    return *reinterpret_cast<uint32_t*>(&h);
}
__device__ __forceinline__ void cp16(uint32_t dst, const void* src) {
    asm volatile("cp.async.cg.shared.global [%0], [%1], 16;" :: "r"(dst), "l"(src));
}
__device__ __forceinline__ void cp_commit() {
    asm volatile("cp.async.commit_group;" ::: "memory");
}
__device__ __forceinline__ void cp_wait1() {
    asm volatile("cp.async.wait_group 1;" ::: "memory");
}

// ---------------------------------------------------------------------------
// prep: (a) convert h -> g_hh fp16, (b) scatter-add distances into g_agg.
// Edge dtype probed (jax randint int64 demotes to int32 when x64 off).
// ---------------------------------------------------------------------------
__global__ void prep_kernel(const float* __restrict__ h,
                            const int* __restrict__ edges_i32,
                            const float* __restrict__ dist,
                            int n_nodes, int E) {
    __shared__ int sstride;
    if (threadIdx.x == 0) {
        bool all_zero = true;
        int probe = E < 16 ? E : 16;
        for (int j = 0; j < probe; j++)
            if (edges_i32[2 * j + 1] != 0) { all_zero = false; break; }
        sstride = all_zero ? 2 : 1;
    }
    __syncthreads();
    int stride = sstride;
    int gid = blockIdx.x * blockDim.x + threadIdx.x;
    int conv_n = n_nodes * 32;            // float4 units
    int scat_n = (E + 3) >> 2;
    int total = conv_n > scat_n ? conv_n : scat_n;
    for (int i = gid; i < total; i += gridDim.x * blockDim.x) {
        if (i < conv_n) {
            float4 v = __ldg((const float4*)&h[(size_t)i * 4]);
            uint2 pk;
            pk.x = packh2(v.x, v.y);
            pk.y = packh2(v.z, v.w);
            *reinterpret_cast<uint2*>(&g_hh[(size_t)i * 4]) = pk;
        }
        if (i < scat_n) {
            int i4 = i * 4;
            if (i4 + 3 < E) {
                float4 d = __ldg((const float4*)&dist[i4]);
                int r0, r1, r2, r3;
                if (stride == 1) {
                    int4 r = __ldg((const int4*)&edges_i32[i4]);
                    r0 = r.x; r1 = r.y; r2 = r.z; r3 = r.w;
                } else {
                    int4 ra = __ldg((const int4*)&edges_i32[2 * i4]);
                    int4 rb = __ldg((const int4*)&edges_i32[2 * i4 + 4]);
                    r0 = ra.x; r1 = ra.z; r2 = rb.x; r3 = rb.z;
                }
                atomicAdd(&g_agg[r0], d.x);
                atomicAdd(&g_agg[r1], d.y);
                atomicAdd(&g_agg[r2], d.z);
                atomicAdd(&g_agg[r3], d.w);
            } else {
                for (int j = i4; j < E; j++)
                    atomicAdd(&g_agg[edges_i32[(long long)j * stride]], dist[j]);
            }
        }
    }
}

using FragA = wmma::fragment<wmma::matrix_a, 16, 16, 16, __half, wmma::row_major>;
using FragB = wmma::fragment<wmma::matrix_b, 16, 16, 16, __half, wmma::row_major>;
using FragC = wmma::fragment<wmma::accumulator, 16, 16, 16, float>;

// acc[2][2] += A[r0..+31][0..127] @ B[0..127][c0..+31], fp16 smem, ping-pong.
__device__ __forceinline__ void gemm_fp16(const __half* __restrict__ as,
                                          const __half* __restrict__ bs,
                                          int r0, int c0, FragC acc[2][2]) {
    FragA af[2][2];
    FragB bf[2][2];
    wmma::load_matrix_sync(af[0][0], as + (size_t)r0 * LDH, LDH);
    wmma::load_matrix_sync(af[0][1], as + (size_t)(r0 + 16) * LDH, LDH);
    wmma::load_matrix_sync(bf[0][0], bs + c0, LDH);
    wmma::load_matrix_sync(bf[0][1], bs + c0 + 16, LDH);
#pragma unroll
    for (int ks = 0; ks < 8; ks++) {
        int cur = ks & 1, nxt = cur ^ 1;
        if (ks < 7) {
            int k = (ks + 1) * 16;
            wmma::load_matrix_sync(af[nxt][0], as + (size_t)r0 * LDH + k, LDH);
            wmma::load_matrix_sync(af[nxt][1], as + (size_t)(r0 + 16) * LDH + k, LDH);
            wmma::load_matrix_sync(bf[nxt][0], bs + (size_t)k * LDH + c0, LDH);
            wmma::load_matrix_sync(bf[nxt][1], bs + (size_t)k * LDH + c0 + 16, LDH);
        }
#pragma unroll
        for (int i = 0; i < 2; i++)
#pragma unroll
            for (int j = 0; j < 2; j++)
                wmma::mma_sync(acc[i][j], af[cur][i], bf[cur][j], acc[i][j]);
    }
}

// ---------------------------------------------------------------------------
// smem layout (bytes)
// ---------------------------------------------------------------------------
#define SM_W1   0                       // half[128*LDH] 34816
#define SM_W2   34816
#define SM_X0   69632
#define SM_X1   104448
#define SM_TH   139264
#define SM_W1R  174080                  // f32[128]
#define SM_B1   174592
#define SM_B2   175104
#define SM_AGG  175616                  // f32[128]
#define SM_IOTA 176128                  // f32[256]
#define SM_TOT  177152

// ---------------------------------------------------------------------------
// Fused node MLP (fp16 TC, fp32 accum), 16 warps, double-buffered fp16 fill:
//   t = silu(h@W1[:128] + agg*W1[128] + b1);  out = h + t@W2 + b2
// ---------------------------------------------------------------------------
__global__ void __launch_bounds__(THREADS, 1)
mlp_kernel(const float* __restrict__ W1, const float* __restrict__ b1,
           const float* __restrict__ W2, const float* __restrict__ b2,
           float* __restrict__ out, int n_nodes, int n_tiles)
{
    extern __shared__ char sm[];
    __half* w1h = (__half*)(sm + SM_W1);
    __half* w2h = (__half*)(sm + SM_W2);
    __half* xb[2] = { (__half*)(sm + SM_X0), (__half*)(sm + SM_X1) };
    __half* th  = (__half*)(sm + SM_TH);
    float*  w1r = (float*)(sm + SM_W1R);
    float*  b1s = (float*)(sm + SM_B1);
    float*  b2s = (float*)(sm + SM_B2);
    float*  sagg = (float*)(sm + SM_AGG);
    float*  iota = (float*)(sm + SM_IOTA);

    const int tid  = threadIdx.x;
    const int warp = tid >> 5;
    const int r0   = (warp >> 2) * 32;
    const int c0   = (warp & 3) * 32;
    const uint32_t xbs[2] = { (uint32_t)__cvta_generic_to_shared(xb[0]),
                              (uint32_t)__cvta_generic_to_shared(xb[1]) };

    // ---- prologue fill: tile0 -> buffer 0 (fp16 straight from g_hh) ----
    if (blockIdx.x < n_tiles) {
        int base = blockIdx.x * M_TILE;
#pragma unroll
        for (int t = 0; t < 4; t++) {
            int idx = tid + t * THREADS;            // 0..2047
            int m = idx >> 4, s = (idx & 15) << 3;  // 16B chunks of a 256B row
            cp16(xbs[0] + (uint32_t)(m * LDH + s) * 2,
                 &g_hh[(size_t)(base + m) * HID + s]);
        }
    }
    cp_commit();

    // ---- stage weights (fp16) + vectors (fp32) ----
    for (int idx = tid; idx < 128 * 32; idx += THREADS) {
        int k = idx >> 5, c4 = (idx & 31) << 2;
        float4 v1 = __ldg((const float4*)&W1[k * HID + c4]);
        float4 v2 = __ldg((const float4*)&W2[k * HID + c4]);
        uint2 pk, qk;
        pk.x = packh2(v1.x, v1.y);
        pk.y = packh2(v1.z, v1.w);
        qk.x = packh2(v2.x, v2.y);
        qk.y = packh2(v2.z, v2.w);
        *reinterpret_cast<uint2*>(&w1h[(size_t)k * LDH + c4]) = pk;
        *reinterpret_cast<uint2*>(&w2h[(size_t)k * LDH + c4]) = qk;
    }
    if (tid < 32) {
        *(float4*)&w1r[tid * 4] = __ldg((const float4*)&W1[128 * HID + tid * 4]);
        *(float4*)&b1s[tid * 4] = __ldg((const float4*)&b1[tid * 4]);
        *(float4*)&b2s[tid * 4] = __ldg((const float4*)&b2[tid * 4]);
    }
    if (tid < 256) iota[tid] = (float)tid;
    __syncthreads();

    // decode accumulator fragment layout once (layout-agnostic)
    int dr[FragC::num_elements], dc[FragC::num_elements];
    {
        FragC idxf;
        wmma::load_matrix_sync(idxf, iota, 16, wmma::mem_row_major);
#pragma unroll
        for (int e = 0; e < idxf.num_elements; e++) {
            int v = __float2int_rn(idxf.x[e]);
            dr[e] = v >> 4;
            dc[e] = v & 15;
        }
    }

    int it = 0;
    for (int tile = blockIdx.x; tile < n_tiles; tile += gridDim.x, it++) {
        const int base = tile * M_TILE;
        const int cur = it & 1;
        const __half* xc = xb[cur];

        __syncthreads();   // S1: prev tile fully consumed (other buffer free)

        // issue next tile's fill into the other buffer
        int nt = tile + gridDim.x;
        if (nt < n_tiles) {
            int nb = nt * M_TILE;
#pragma unroll
            for (int t = 0; t < 4; t++) {
                int idx = tid + t * THREADS;
                int m = idx >> 4, s = (idx & 15) << 3;
                cp16(xbs[cur ^ 1] + (uint32_t)(m * LDH + s) * 2,
                     &g_hh[(size_t)(nb + m) * HID + s]);
            }
        }
        cp_commit();

        // agg slice (fp32) + re-zero g_agg
        if (tid < M_TILE) {
            int gn = base + tid;
            float a = 0.f;
            if (gn < n_nodes) { a = g_agg[gn] * 0.01f; g_agg[gn] = 0.f; }
            sagg[tid] = a;
        }
        cp_wait1();        // this tile's fill (issued last iteration) complete
        __syncthreads();   // S2: fill + sagg visible

        // ---- GEMM1: D1 = X @ W1[:128] ----
        FragC acc[2][2];
#pragma unroll
        for (int i = 0; i < 2; i++)
#pragma unroll
            for (int j = 0; j < 2; j++) wmma::fill_fragment(acc[i][j], 0.0f);
        gemm_fp16(xc, w1h, r0, c0, acc);

        // ---- epilogue1 (fp32 regs): th = silu(D1 + agg[r]*w1r[c] + b1[c]) ----
#pragma unroll
        for (int i = 0; i < 2; i++)
#pragma unroll
            for (int j = 0; j < 2; j++)
#pragma unroll
                for (int e = 0; e < FragC::num_elements; e++) {
                    int r = r0 + i * 16 + dr[e];
                    int c = c0 + j * 16 + dc[e];
                    float v = acc[i][j].x[e] + sagg[r] * w1r[c] + b1s[c];
                    th[(size_t)r * LDH + c] = __float2half_rn(silu(v));
                }
        __syncthreads();   // S3: th complete before GEMM2 reads

        // ---- GEMM2: U = T @ W2 ----
        FragC acc2[2][2];
#pragma unroll
        for (int i = 0; i < 2; i++)
#pragma unroll
            for (int j = 0; j < 2; j++) wmma::fill_fragment(acc2[i][j], 0.0f);
        gemm_fp16(th, w2h, r0, c0, acc2);

        // ---- store: out = residual(xc fp16) + U + b2, float2-paired ----
#pragma unroll
        for (int i = 0; i < 2; i++)
#pragma unroll
            for (int j = 0; j < 2; j++) {
#pragma unroll
                for (int e = 0; e < FragC::num_elements; e += 2) {
                    int r = r0 + i * 16 + dr[e];
                    int c = c0 + j * 16 + dc[e];
                    int gn = base + r;
                    bool paired = (dr[e + 1] == dr[e]) &&
                                  (dc[e + 1] == dc[e] + 1) && ((c & 1) == 0);
                    if (paired) {
                        if (gn < n_nodes) {
                            __half2 hv = *(const __half2*)&xc[(size_t)r * LDH + c];
                            float2 o = make_float2(
                                acc2[i][j].x[e]     + __low2float(hv)  + b2s[c],
                                acc2[i][j].x[e + 1] + __high2float(hv) + b2s[c + 1]);
                            *(float2*)&out[(size_t)gn * HID + c] = o;
                        }
                    } else {
                        if (gn < n_nodes) {
                            float hv = __half2float(xc[(size_t)r * LDH + c]);
                            out[(size_t)gn * HID + c] = acc2[i][j].x[e] + hv + b2s[c];
                        }
                        int r1 = r0 + i * 16 + dr[e + 1];
                        int c1 = c0 + j * 16 + dc[e + 1];
                        int gn1 = base + r1;
                        if (gn1 < n_nodes) {
                            float hv = __half2float(xc[(size_t)r1 * LDH + c1]);
                            out[(size_t)gn1 * HID + c1] =
                                acc2[i][j].x[e + 1] + hv + b2s[c1];
                        }
                    }
                }
            }
    }
}

// ---------------------------------------------------------------------------
extern "C" void kernel_launch(void* const* d_in, const int* in_sizes, int n_in,
                              void* d_out, int out_size) {
    const float* h    = (const float*)d_in[0];
    const int*   edg  = (const int*)  d_in[1];
    const float* dist = (const float*)d_in[2];
    const float* W1   = (const float*)d_in[9];   // W_n1 [129,128]
    const float* b1   = (const float*)d_in[10];
    const float* W2   = (const float*)d_in[11];  // W_n2 [128,128]
    const float* b2   = (const float*)d_in[12];
    float* out = (float*)d_out;

    int n_nodes = in_sizes[0] / HID;
    int E       = in_sizes[2];

    int conv_n = n_nodes * 32;
    int scat_n = (E + 3) / 4;
    int total  = conv_n > scat_n ? conv_n : scat_n;
    prep_kernel<<<(total + 255) / 256, 256>>>(h, edg, dist, n_nodes, E);

    cudaFuncSetAttribute(mlp_kernel,
                         cudaFuncAttributeMaxDynamicSharedMemorySize, SM_TOT);
    int sms = 148;
    cudaDeviceGetAttribute(&sms, cudaDevAttrMultiProcessorCount, 0);
    int n_tiles = (n_nodes + M_TILE - 1) / M_TILE;
    int grid = n_tiles < sms ? n_tiles : sms;
    mlp_kernel<<<grid, THREADS, SM_TOT>>>(W1, b1, W2, b2, out, n_nodes, n_tiles);
}

// round 12
// speedup vs baseline: 1.2579x; 1.2187x over previous
#include <cuda_runtime.h>
#include <cuda_fp16.h>
#include <mma.h>
#include <cstdint>

using namespace nvcuda;

#define HID     128
#define M_TILE  128
#define THREADS 512
#define LDH     136     // half stride: 272B ≡ 16 mod 128 -> conflict-free LDSM

// Scratch: per-node aggregate. Zero at module load; mlp re-zeroes after
// reading so the invariant holds across CUDA-graph replays.
__device__ float g_agg[65536];

// silu via single-MUFU tanh: sigmoid(x) = 0.5*tanh(x/2) + 0.5
__device__ __forceinline__ float silu(float x) {
    float t;
    asm("tanh.approx.f32 %0, %1;" : "=f"(t) : "f"(x * 0.5f));
    return x * (0.5f * t + 0.5f);
}

// ---------------------------------------------------------------------------
// scatter-add distances into g_agg[row[e]], 4 edges per thread.
// Edge dtype probed: jax randint int64 silently demotes to int32 when x64 is
// off; true int64 buffers have all-zero high words (indices < 50000).
// ---------------------------------------------------------------------------
__global__ void scatter_kernel(const int* __restrict__ edges_i32,
                               const float* __restrict__ dist, int E) {
    __shared__ int sstride;
    if (threadIdx.x == 0) {
        bool all_zero = true;
        int probe = E < 16 ? E : 16;
        for (int j = 0; j < probe; j++)
            if (edges_i32[2 * j + 1] != 0) { all_zero = false; break; }
        sstride = all_zero ? 2 : 1;
    }
    __syncthreads();
    int stride = sstride;
    int i4 = (blockIdx.x * blockDim.x + threadIdx.x) * 4;
    if (i4 + 3 < E) {
        float4 d = __ldg((const float4*)&dist[i4]);
        int r0, r1, r2, r3;
        if (stride == 1) {
            int4 r = __ldg((const int4*)&edges_i32[i4]);
            r0 = r.x; r1 = r.y; r2 = r.z; r3 = r.w;
        } else {
            int4 ra = __ldg((const int4*)&edges_i32[2 * i4]);
            int4 rb = __ldg((const int4*)&edges_i32[2 * i4 + 4]);
            r0 = ra.x; r1 = ra.z; r2 = rb.x; r3 = rb.z;
        }
        atomicAdd(&g_agg[r0], d.x);
        atomicAdd(&g_agg[r1], d.y);
        atomicAdd(&g_agg[r2], d.z);
        atomicAdd(&g_agg[r3], d.w);
    } else {
        for (int j = i4; j < E; j++) {
            int r = edges_i32[(long long)j * stride];
            atomicAdd(&g_agg[r], dist[j]);
        }
    }
}

using FragA = wmma::fragment<wmma::matrix_a, 16, 16, 16, __half, wmma::row_major>;
using FragB = wmma::fragment<wmma::matrix_b, 16, 16, 16, __half, wmma::row_major>;
using FragC = wmma::fragment<wmma::accumulator, 16, 16, 16, float>;

// acc[2][2] += A[r0..+31][0..127] @ B[0..127][c0..+31], fp16 smem, ping-pong.
__device__ __forceinline__ void gemm_fp16(const __half* __restrict__ as,
                                          const __half* __restrict__ bs,
                                          int r0, int c0, FragC acc[2][2]) {
    FragA af[2][2];
    FragB bf[2][2];
    wmma::load_matrix_sync(af[0][0], as + (size_t)r0 * LDH, LDH);
    wmma::load_matrix_sync(af[0][1], as + (size_t)(r0 + 16) * LDH, LDH);
    wmma::load_matrix_sync(bf[0][0], bs + c0, LDH);
    wmma::load_matrix_sync(bf[0][1], bs + c0 + 16, LDH);
#pragma unroll
    for (int ks = 0; ks < 8; ks++) {
        int cur = ks & 1, nxt = cur ^ 1;
        if (ks < 7) {
            int k = (ks + 1) * 16;
            wmma::load_matrix_sync(af[nxt][0], as + (size_t)r0 * LDH + k, LDH);
            wmma::load_matrix_sync(af[nxt][1], as + (size_t)(r0 + 16) * LDH + k, LDH);
            wmma::load_matrix_sync(bf[nxt][0], bs + (size_t)k * LDH + c0, LDH);
            wmma::load_matrix_sync(bf[nxt][1], bs + (size_t)k * LDH + c0 + 16, LDH);
        }
#pragma unroll
        for (int i = 0; i < 2; i++)
#pragma unroll
            for (int j = 0; j < 2; j++)
                wmma::mma_sync(acc[i][j], af[cur][i], bf[cur][j], acc[i][j]);
    }
}

// ---------------------------------------------------------------------------
// smem layout (bytes)
// ---------------------------------------------------------------------------
#define SM_W1H   0                      // half[128*LDH] 34816
#define SM_W2H   34816
#define SM_XH    69632
#define SM_TH    104448
#define SM_STAGE 139264                 // f32[128][128] = 65536
#define SM_W1R   204800                 // f32[128]
#define SM_B1    205312
#define SM_B2    205824
#define SM_AGG   206336
#define SM_IOTA  206848                 // f32[256]
#define SM_TOTAL 207872

// cp.async 16B with zero-fill when src_sz == 0
__device__ __forceinline__ void cp_async16(void* dst_smem, const void* src, int src_sz) {
    unsigned d = (unsigned)__cvta_generic_to_shared(dst_smem);
    asm volatile("cp.async.cg.shared.global [%0], [%1], 16, %2;"
                 :: "r"(d), "l"(src), "r"(src_sz));
}
__device__ __forceinline__ void cp_commit() {
    asm volatile("cp.async.commit_group;" ::: "memory");
}
__device__ __forceinline__ void cp_wait0() {
    asm volatile("cp.async.wait_group 0;" ::: "memory");
}

// issue the fp32 h-tile load for `tile` into stage
__device__ __forceinline__ void issue_stage(float* stagef, const float* h,
                                            int base, int n_nodes, int tid) {
#pragma unroll
    for (int t = 0; t < 8; t++) {
        int idx = tid + t * THREADS;           // 0..4095
        int m = idx >> 5, c4 = (idx & 31) << 2;
        int gn = base + m;
        int ok = (gn < n_nodes);
        const float* src = h + (size_t)(ok ? gn : 0) * HID + c4;
        cp_async16(&stagef[m * HID + c4], src, ok ? 16 : 0);
    }
    cp_commit();
}

// ---------------------------------------------------------------------------
// Fused node MLP (fp16 TC, fp32 accum), cp.async tile pipeline:
//   t = silu(h@W1[:128] + agg*W1[128] + b1);  out = h + t@W2 + b2
// ---------------------------------------------------------------------------
__global__ void __launch_bounds__(THREADS, 1)
mlp_kernel(const float* __restrict__ h,
           const float* __restrict__ W1, const float* __restrict__ b1,
           const float* __restrict__ W2, const float* __restrict__ b2,
           float* __restrict__ out, int n_nodes, int n_tiles)
{
    extern __shared__ char sm[];
    __half* w1h   = (__half*)(sm + SM_W1H);
    __half* w2h   = (__half*)(sm + SM_W2H);
    __half* xh    = (__half*)(sm + SM_XH);
    __half* th    = (__half*)(sm + SM_TH);
    float*  stagef = (float*)(sm + SM_STAGE);
    float*  w1r   = (float*)(sm + SM_W1R);
    float*  b1s   = (float*)(sm + SM_B1);
    float*  b2s   = (float*)(sm + SM_B2);
    float*  sagg  = (float*)(sm + SM_AGG);
    float*  iota  = (float*)(sm + SM_IOTA);

    const int tid  = threadIdx.x;
    const int warp = tid >> 5;
    const int r0   = (warp >> 2) * 32;
    const int c0   = (warp & 3) * 32;

    // prologue: start streaming tile 0's h before anything else
    if (blockIdx.x < n_tiles)
        issue_stage(stagef, h, blockIdx.x * M_TILE, n_nodes, tid);

    // ---- stage weights (fp16) + vectors (fp32) once per CTA ----
    for (int idx = tid; idx < 128 * 32; idx += THREADS) {
        int k = idx >> 5, c4 = (idx & 31) << 2;
        float4 v1 = __ldg((const float4*)&W1[k * HID + c4]);
        float4 v2 = __ldg((const float4*)&W2[k * HID + c4]);
        __half2 p0 = __floats2half2_rn(v1.x, v1.y);
        __half2 p1 = __floats2half2_rn(v1.z, v1.w);
        __half2 q0 = __floats2half2_rn(v2.x, v2.y);
        __half2 q1 = __floats2half2_rn(v2.z, v2.w);
        uint2 pk, qk;
        pk.x = *reinterpret_cast<unsigned*>(&p0);
        pk.y = *reinterpret_cast<unsigned*>(&p1);
        qk.x = *reinterpret_cast<unsigned*>(&q0);
        qk.y = *reinterpret_cast<unsigned*>(&q1);
        *reinterpret_cast<uint2*>(&w1h[(size_t)k * LDH + c4]) = pk;
        *reinterpret_cast<uint2*>(&w2h[(size_t)k * LDH + c4]) = qk;
    }
    if (tid < 32) {
        *(float4*)&w1r[tid * 4] = __ldg((const float4*)&W1[128 * HID + tid * 4]);
        *(float4*)&b1s[tid * 4] = __ldg((const float4*)&b1[tid * 4]);
        *(float4*)&b2s[tid * 4] = __ldg((const float4*)&b2[tid * 4]);
    }
    if (tid < 256) iota[tid] = (float)tid;
    __syncthreads();

    // decode accumulator fragment layout once (layout-agnostic)
    int dr[FragC::num_elements], dc[FragC::num_elements];
    {
        FragC idxf;
        wmma::load_matrix_sync(idxf, iota, 16, wmma::mem_row_major);
#pragma unroll
        for (int e = 0; e < idxf.num_elements; e++) {
            int v = __float2int_rn(idxf.x[e]);
            dr[e] = v >> 4;
            dc[e] = v & 15;
        }
    }

    for (int tile = blockIdx.x; tile < n_tiles; tile += gridDim.x) {
        const int base = tile * M_TILE;
        const int next = tile + gridDim.x;
        const bool full = (base + M_TILE <= n_nodes);

        cp_wait0();
        __syncthreads();   // stage ready; previous th reads complete

        // ---- convert stage (fp32) -> xh (fp16); agg slice ----
#pragma unroll
        for (int t = 0; t < 8; t++) {
            int idx = tid + t * THREADS;
            int m = idx >> 5, c4 = (idx & 31) << 2;
            float4 v = *(const float4*)&stagef[m * HID + c4];
            __half2 p0 = __floats2half2_rn(v.x, v.y);
            __half2 p1 = __floats2half2_rn(v.z, v.w);
            uint2 pk;
            pk.x = *reinterpret_cast<unsigned*>(&p0);
            pk.y = *reinterpret_cast<unsigned*>(&p1);
            *reinterpret_cast<uint2*>(&xh[(size_t)m * LDH + c4]) = pk;
        }
        if (tid < 128) {
            int gn = base + tid;
            float a = 0.f;
            if (gn < n_nodes) { a = g_agg[gn] * 0.01f; g_agg[gn] = 0.f; }
            sagg[tid] = a;
        }
        __syncthreads();

        // ---- GEMM1: D1 = X @ W1[:128] ----
        FragC acc[2][2];
#pragma unroll
        for (int i = 0; i < 2; i++)
#pragma unroll
            for (int j = 0; j < 2; j++) wmma::fill_fragment(acc[i][j], 0.0f);
        gemm_fp16(xh, w1h, r0, c0, acc);

        // ---- epilogue1 (fp32 regs): t = silu(D1 + agg[r]*w1r[c] + b1[c]) ----
        // paired __half2 stores where the fragment layout allows (it does on
        // sm_8x/9x/10x row-major fp32 accum: elements come in (c, c+1) pairs)
#pragma unroll
        for (int i = 0; i < 2; i++)
#pragma unroll
            for (int j = 0; j < 2; j++)
#pragma unroll
                for (int e = 0; e < FragC::num_elements; e += 2) {
                    int r = r0 + i * 16 + dr[e];
                    int c = c0 + j * 16 + dc[e];
                    bool paired = (dr[e + 1] == dr[e]) &&
                                  (dc[e + 1] == dc[e] + 1) && ((c & 1) == 0);
                    float aggv = sagg[r];
                    float v0 = acc[i][j].x[e] + aggv * w1r[c] + b1s[c];
                    if (paired) {
                        float v1 = acc[i][j].x[e + 1] + aggv * w1r[c + 1] + b1s[c + 1];
                        *(__half2*)&th[(size_t)r * LDH + c] =
                            __floats2half2_rn(silu(v0), silu(v1));
                    } else {
                        th[(size_t)r * LDH + c] = __float2half_rn(silu(v0));
                        int r1 = r0 + i * 16 + dr[e + 1];
                        int c1 = c0 + j * 16 + dc[e + 1];
                        float v1 = acc[i][j].x[e + 1] + sagg[r1] * w1r[c1] + b1s[c1];
                        th[(size_t)r1 * LDH + c1] = __float2half_rn(silu(v1));
                    }
                }

        // ---- residual from stage (fp32, still valid) into acc2 ----
        FragC acc2[2][2];
#pragma unroll
        for (int i = 0; i < 2; i++)
#pragma unroll
            for (int j = 0; j < 2; j++)
                wmma::load_matrix_sync(acc2[i][j],
                    &stagef[(size_t)(r0 + i * 16) * HID + c0 + j * 16],
                    HID, wmma::mem_row_major);

        __syncthreads();   // th complete; all stage reads done

        // ---- start streaming next tile's h into stage ----
        if (next < n_tiles) issue_stage(stagef, h, next * M_TILE, n_nodes, tid);

        // ---- GEMM2: out = residual + T @ W2 (+ b2) ----
        gemm_fp16(th, w2h, r0, c0, acc2);

        if (full) {
#pragma unroll
            for (int i = 0; i < 2; i++)
#pragma unroll
                for (int j = 0; j < 2; j++) {
#pragma unroll
                    for (int e = 0; e < FragC::num_elements; e++)
                        acc2[i][j].x[e] += b2s[c0 + j * 16 + dc[e]];
                    wmma::store_matrix_sync(
                        &out[(size_t)(base + r0 + i * 16) * HID + c0 + j * 16],
                        acc2[i][j], HID, wmma::mem_row_major);
                }
        } else {
            // partial last tile: guarded scalar stores (residual already in acc2)
#pragma unroll
            for (int i = 0; i < 2; i++)
#pragma unroll
                for (int j = 0; j < 2; j++)
#pragma unroll
                    for (int e = 0; e < FragC::num_elements; e++) {
                        int gn = base + r0 + i * 16 + dr[e];
                        int c  = c0 + j * 16 + dc[e];
                        if (gn < n_nodes)
                            out[(size_t)gn * HID + c] = acc2[i][j].x[e] + b2s[c];
                    }
        }
    }
}

// ---------------------------------------------------------------------------
extern "C" void kernel_launch(void* const* d_in, const int* in_sizes, int n_in,
                              void* d_out, int out_size) {
    const float* h    = (const float*)d_in[0];
    const int*   edg  = (const int*)  d_in[1];
    const float* dist = (const float*)d_in[2];
    const float* W1   = (const float*)d_in[9];   // W_n1 [129,128]
    const float* b1   = (const float*)d_in[10];
    const float* W2   = (const float*)d_in[11];  // W_n2 [128,128]
    const float* b2   = (const float*)d_in[12];
    float* out = (float*)d_out;

    int n_nodes = in_sizes[0] / HID;
    int E       = in_sizes[2];

    int sblocks = ((E + 3) / 4 + 255) / 256;
    scatter_kernel<<<sblocks, 256>>>(edg, dist, E);

    cudaFuncSetAttribute(mlp_kernel,
                         cudaFuncAttributeMaxDynamicSharedMemorySize, SM_TOTAL);
    int sms = 148;
    cudaDeviceGetAttribute(&sms, cudaDevAttrMultiProcessorCount, 0);
    int n_tiles = (n_nodes + M_TILE - 1) / M_TILE;
    int grid = n_tiles < sms ? n_tiles : sms;
    mlp_kernel<<<grid, THREADS, SM_TOTAL>>>(h, W1, b1, W2, b2, out,
                                            n_nodes, n_tiles);
}

// round 13
// speedup vs baseline: 1.2897x; 1.0253x over previous
#include <cuda_runtime.h>
#include <cuda_fp16.h>
#include <mma.h>
#include <cstdint>

using namespace nvcuda;

#define HID     128
#define M_TILE  128
#define THREADS 512
#define LDH     136     // half stride: 272B ≡ 16 mod 128 -> conflict-free LDSM

// Scratch: per-node aggregate. Zero at module load; mlp re-zeroes after
// reading so the invariant holds across CUDA-graph replays.
__device__ float g_agg[65536];

// silu via single-MUFU tanh: sigmoid(x) = 0.5*tanh(x/2) + 0.5
__device__ __forceinline__ float silu(float x) {
    float t;
    asm("tanh.approx.f32 %0, %1;" : "=f"(t) : "f"(x * 0.5f));
    return x * (0.5f * t + 0.5f);
}

// ---------------------------------------------------------------------------
// scatter-add distances into g_agg[row[e]], 4 edges per thread.
// Edge dtype probed: jax randint int64 silently demotes to int32 when x64 is
// off; true int64 buffers have all-zero high words (indices < 50000).
// ---------------------------------------------------------------------------
__global__ void scatter_kernel(const int* __restrict__ edges_i32,
                               const float* __restrict__ dist, int E) {
    __shared__ int sstride;
    if (threadIdx.x == 0) {
        bool all_zero = true;
        int probe = E < 16 ? E : 16;
        for (int j = 0; j < probe; j++)
            if (edges_i32[2 * j + 1] != 0) { all_zero = false; break; }
        sstride = all_zero ? 2 : 1;
    }
    __syncthreads();
    int stride = sstride;
    int i4 = (blockIdx.x * blockDim.x + threadIdx.x) * 4;
    if (i4 + 3 < E) {
        float4 d = __ldg((const float4*)&dist[i4]);
        int r0, r1, r2, r3;
        if (stride == 1) {
            int4 r = __ldg((const int4*)&edges_i32[i4]);
            r0 = r.x; r1 = r.y; r2 = r.z; r3 = r.w;
        } else {
            int4 ra = __ldg((const int4*)&edges_i32[2 * i4]);
            int4 rb = __ldg((const int4*)&edges_i32[2 * i4 + 4]);
            r0 = ra.x; r1 = ra.z; r2 = rb.x; r3 = rb.z;
        }
        atomicAdd(&g_agg[r0], d.x);
        atomicAdd(&g_agg[r1], d.y);
        atomicAdd(&g_agg[r2], d.z);
        atomicAdd(&g_agg[r3], d.w);
    } else {
        for (int j = i4; j < E; j++) {
            int r = edges_i32[(long long)j * stride];
            atomicAdd(&g_agg[r], dist[j]);
        }
    }
}

using FragA = wmma::fragment<wmma::matrix_a, 16, 16, 16, __half, wmma::row_major>;
using FragB = wmma::fragment<wmma::matrix_b, 16, 16, 16, __half, wmma::row_major>;
using FragC = wmma::fragment<wmma::accumulator, 16, 16, 16, float>;

// acc[2][2] += A[r0..+31][0..127] @ B[0..127][c0..+31], fp16 smem, ping-pong.
__device__ __forceinline__ void gemm_fp16(const __half* __restrict__ as,
                                          const __half* __restrict__ bs,
                                          int r0, int c0, FragC acc[2][2]) {
    FragA af[2][2];
    FragB bf[2][2];
    wmma::load_matrix_sync(af[0][0], as + (size_t)r0 * LDH, LDH);
    wmma::load_matrix_sync(af[0][1], as + (size_t)(r0 + 16) * LDH, LDH);
    wmma::load_matrix_sync(bf[0][0], bs + c0, LDH);
    wmma::load_matrix_sync(bf[0][1], bs + c0 + 16, LDH);
#pragma unroll
    for (int ks = 0; ks < 8; ks++) {
        int cur = ks & 1, nxt = cur ^ 1;
        if (ks < 7) {
            int k = (ks + 1) * 16;
            wmma::load_matrix_sync(af[nxt][0], as + (size_t)r0 * LDH + k, LDH);
            wmma::load_matrix_sync(af[nxt][1], as + (size_t)(r0 + 16) * LDH + k, LDH);
            wmma::load_matrix_sync(bf[nxt][0], bs + (size_t)k * LDH + c0, LDH);
            wmma::load_matrix_sync(bf[nxt][1], bs + (size_t)k * LDH + c0 + 16, LDH);
        }
#pragma unroll
        for (int i = 0; i < 2; i++)
#pragma unroll
            for (int j = 0; j < 2; j++)
                wmma::mma_sync(acc[i][j], af[cur][i], bf[cur][j], acc[i][j]);
    }
}

// ---------------------------------------------------------------------------
// smem layout (bytes)
// ---------------------------------------------------------------------------
#define SM_W1H   0                      // half[128*LDH] 34816
#define SM_W2H   34816
#define SM_XH    69632
#define SM_TH    104448
#define SM_STAGE 139264                 // f32[128][128] = 65536
#define SM_W1R   204800                 // f32[128]
#define SM_B1    205312
#define SM_B2    205824
#define SM_AGG   206336
#define SM_IOTA  206848                 // f32[256]
#define SM_TOTAL 207872

// cp.async 16B with zero-fill when src_sz == 0
__device__ __forceinline__ void cp_async16(void* dst_smem, const void* src, int src_sz) {
    unsigned d = (unsigned)__cvta_generic_to_shared(dst_smem);
    asm volatile("cp.async.cg.shared.global [%0], [%1], 16, %2;"
                 :: "r"(d), "l"(src), "r"(src_sz));
}
__device__ __forceinline__ void cp_commit() {
    asm volatile("cp.async.commit_group;" ::: "memory");
}
__device__ __forceinline__ void cp_wait0() {
    asm volatile("cp.async.wait_group 0;" ::: "memory");
}
// named barrier over one 128-thread row group (ids 1..4; 0 = syncthreads)
__device__ __forceinline__ void bar_group(int id) {
    asm volatile("bar.sync %0, 128;" :: "r"(id) : "memory");
}

// issue the fp32 h-tile load for this GROUP's 32 rows into stage
__device__ __forceinline__ void issue_stage_g(float* stagef, const float* h,
                                              int base, int n_nodes,
                                              int g, int wtid) {
#pragma unroll
    for (int t = 0; t < 8; t++) {
        int idx = wtid + t * 128;              // 0..1023: 32 rows x 32 float4
        int m = g * 32 + (idx >> 5);
        int c4 = (idx & 31) << 2;
        int gn = base + m;
        int ok = (gn < n_nodes);
        const float* src = h + (size_t)(ok ? gn : 0) * HID + c4;
        cp_async16(&stagef[m * HID + c4], src, ok ? 16 : 0);
    }
    cp_commit();
}

// ---------------------------------------------------------------------------
// Fused node MLP (fp16 TC, fp32 accum). 4 independent 4-warp pipelines per
// CTA (row groups of 32 rows), synced by named barriers only — engines skew
// to fill each other's latency. t = silu(h@W1k + agg*w1r + b1); out = h+t@W2+b2
// ---------------------------------------------------------------------------
__global__ void __launch_bounds__(THREADS, 1)
mlp_kernel(const float* __restrict__ h,
           const float* __restrict__ W1, const float* __restrict__ b1,
           const float* __restrict__ W2, const float* __restrict__ b2,
           float* __restrict__ out, int n_nodes, int n_tiles)
{
    extern __shared__ char sm[];
    __half* w1h   = (__half*)(sm + SM_W1H);
    __half* w2h   = (__half*)(sm + SM_W2H);
    __half* xh    = (__half*)(sm + SM_XH);
    __half* th    = (__half*)(sm + SM_TH);
    float*  stagef = (float*)(sm + SM_STAGE);
    float*  w1r   = (float*)(sm + SM_W1R);
    float*  b1s   = (float*)(sm + SM_B1);
    float*  b2s   = (float*)(sm + SM_B2);
    float*  sagg  = (float*)(sm + SM_AGG);
    float*  iota  = (float*)(sm + SM_IOTA);

    const int tid  = threadIdx.x;
    const int warp = tid >> 5;
    const int g    = warp >> 2;          // row group 0..3 (owns rows 32g..+31)
    const int wtid = tid & 127;          // thread id within group
    const int bid  = g + 1;              // named barrier id
    const int r0   = g * 32;
    const int c0   = (warp & 3) * 32;

    // prologue: each group streams its own 32 rows of tile 0
    if (blockIdx.x < n_tiles)
        issue_stage_g(stagef, h, blockIdx.x * M_TILE, n_nodes, g, wtid);

    // ---- stage weights (fp16) + vectors (fp32) once per CTA ----
    for (int idx = tid; idx < 128 * 32; idx += THREADS) {
        int k = idx >> 5, c4 = (idx & 31) << 2;
        float4 v1 = __ldg((const float4*)&W1[k * HID + c4]);
        float4 v2 = __ldg((const float4*)&W2[k * HID + c4]);
        __half2 p0 = __floats2half2_rn(v1.x, v1.y);
        __half2 p1 = __floats2half2_rn(v1.z, v1.w);
        __half2 q0 = __floats2half2_rn(v2.x, v2.y);
        __half2 q1 = __floats2half2_rn(v2.z, v2.w);
        uint2 pk, qk;
        pk.x = *reinterpret_cast<unsigned*>(&p0);
        pk.y = *reinterpret_cast<unsigned*>(&p1);
        qk.x = *reinterpret_cast<unsigned*>(&q0);
        qk.y = *reinterpret_cast<unsigned*>(&q1);
        *reinterpret_cast<uint2*>(&w1h[(size_t)k * LDH + c4]) = pk;
        *reinterpret_cast<uint2*>(&w2h[(size_t)k * LDH + c4]) = qk;
    }
    if (tid < 32) {
        *(float4*)&w1r[tid * 4] = __ldg((const float4*)&W1[128 * HID + tid * 4]);
        *(float4*)&b1s[tid * 4] = __ldg((const float4*)&b1[tid * 4]);
        *(float4*)&b2s[tid * 4] = __ldg((const float4*)&b2[tid * 4]);
    }
    if (tid < 256) iota[tid] = (float)tid;
    __syncthreads();   // last full-CTA sync: weights/iota visible to all

    // decode accumulator fragment layout once (layout-agnostic)
    int dr[FragC::num_elements], dc[FragC::num_elements];
    {
        FragC idxf;
        wmma::load_matrix_sync(idxf, iota, 16, wmma::mem_row_major);
#pragma unroll
        for (int e = 0; e < idxf.num_elements; e++) {
            int v = __float2int_rn(idxf.x[e]);
            dr[e] = v >> 4;
            dc[e] = v & 15;
        }
    }

    for (int tile = blockIdx.x; tile < n_tiles; tile += gridDim.x) {
        const int base = tile * M_TILE;
        const int next = tile + gridDim.x;
        const bool full = (base + M_TILE <= n_nodes);

        cp_wait0();
        bar_group(bid);   // stage rows ready; prev tile th/xh reads complete

        // ---- convert group's stage rows (fp32) -> xh (fp16); agg slice ----
#pragma unroll
        for (int t = 0; t < 8; t++) {
            int idx = wtid + t * 128;
            int m = r0 + (idx >> 5), c4 = (idx & 31) << 2;
            float4 v = *(const float4*)&stagef[m * HID + c4];
            __half2 p0 = __floats2half2_rn(v.x, v.y);
            __half2 p1 = __floats2half2_rn(v.z, v.w);
            uint2 pk;
            pk.x = *reinterpret_cast<unsigned*>(&p0);
            pk.y = *reinterpret_cast<unsigned*>(&p1);
            *reinterpret_cast<uint2*>(&xh[(size_t)m * LDH + c4]) = pk;
        }
        if (wtid < 32) {
            int gn = base + r0 + wtid;
            float a = 0.f;
            if (gn < n_nodes) { a = g_agg[gn] * 0.01f; g_agg[gn] = 0.f; }
            sagg[r0 + wtid] = a;
        }
        bar_group(bid);

        // ---- GEMM1: D1 = X[group rows] @ W1[:128] ----
        FragC acc[2][2];
#pragma unroll
        for (int i = 0; i < 2; i++)
#pragma unroll
            for (int j = 0; j < 2; j++) wmma::fill_fragment(acc[i][j], 0.0f);
        gemm_fp16(xh, w1h, r0, c0, acc);

        // ---- epilogue1 (fp32 regs): th = silu(D1 + agg[r]*w1r[c] + b1[c]) ----
#pragma unroll
        for (int i = 0; i < 2; i++)
#pragma unroll
            for (int j = 0; j < 2; j++)
#pragma unroll
                for (int e = 0; e < FragC::num_elements; e += 2) {
                    int r = r0 + i * 16 + dr[e];
                    int c = c0 + j * 16 + dc[e];
                    bool paired = (dr[e + 1] == dr[e]) &&
                                  (dc[e + 1] == dc[e] + 1) && ((c & 1) == 0);
                    float aggv = sagg[r];
                    float v0 = acc[i][j].x[e] + aggv * w1r[c] + b1s[c];
                    if (paired) {
                        float v1 = acc[i][j].x[e + 1] + aggv * w1r[c + 1] + b1s[c + 1];
                        *(__half2*)&th[(size_t)r * LDH + c] =
                            __floats2half2_rn(silu(v0), silu(v1));
                    } else {
                        th[(size_t)r * LDH + c] = __float2half_rn(silu(v0));
                        int r1 = r0 + i * 16 + dr[e + 1];
                        int c1 = c0 + j * 16 + dc[e + 1];
                        float v1 = acc[i][j].x[e + 1] + sagg[r1] * w1r[c1] + b1s[c1];
                        th[(size_t)r1 * LDH + c1] = __float2half_rn(silu(v1));
                    }
                }

        // ---- residual from stage (fp32, group rows) into acc2 ----
        FragC acc2[2][2];
#pragma unroll
        for (int i = 0; i < 2; i++)
#pragma unroll
            for (int j = 0; j < 2; j++)
                wmma::load_matrix_sync(acc2[i][j],
                    &stagef[(size_t)(r0 + i * 16) * HID + c0 + j * 16],
                    HID, wmma::mem_row_major);

        bar_group(bid);   // group's th complete; group's stage reads done

        // ---- stream next tile's group rows into stage ----
        if (next < n_tiles) issue_stage_g(stagef, h, next * M_TILE, n_nodes, g, wtid);

        // ---- GEMM2: out = residual + T[group rows] @ W2 (+ b2) ----
        gemm_fp16(th, w2h, r0, c0, acc2);

        if (full) {
#pragma unroll
            for (int i = 0; i < 2; i++)
#pragma unroll
                for (int j = 0; j < 2; j++) {
#pragma unroll
                    for (int e = 0; e < FragC::num_elements; e++)
                        acc2[i][j].x[e] += b2s[c0 + j * 16 + dc[e]];
                    wmma::store_matrix_sync(
                        &out[(size_t)(base + r0 + i * 16) * HID + c0 + j * 16],
                        acc2[i][j], HID, wmma::mem_row_major);
                }
        } else {
            // partial last tile: guarded scalar stores (residual already in acc2)
#pragma unroll
            for (int i = 0; i < 2; i++)
#pragma unroll
                for (int j = 0; j < 2; j++)
#pragma unroll
                    for (int e = 0; e < FragC::num_elements; e++) {
                        int gn = base + r0 + i * 16 + dr[e];
                        int c  = c0 + j * 16 + dc[e];
                        if (gn < n_nodes)
                            out[(size_t)gn * HID + c] = acc2[i][j].x[e] + b2s[c];
                    }
        }
    }
}

// ---------------------------------------------------------------------------
extern "C" void kernel_launch(void* const* d_in, const int* in_sizes, int n_in,
                              void* d_out, int out_size) {
    const float* h    = (const float*)d_in[0];
    const int*   edg  = (const int*)  d_in[1];
    const float* dist = (const float*)d_in[2];
    const float* W1   = (const float*)d_in[9];   // W_n1 [129,128]
    const float* b1   = (const float*)d_in[10];
    const float* W2   = (const float*)d_in[11];  // W_n2 [128,128]
    const float* b2   = (const float*)d_in[12];
    float* out = (float*)d_out;

    int n_nodes = in_sizes[0] / HID;
    int E       = in_sizes[2];

    int sblocks = ((E + 3) / 4 + 255) / 256;
    scatter_kernel<<<sblocks, 256>>>(edg, dist, E);

    cudaFuncSetAttribute(mlp_kernel,
                         cudaFuncAttributeMaxDynamicSharedMemorySize, SM_TOTAL);
    int sms = 148;
    cudaDeviceGetAttribute(&sms, cudaDevAttrMultiProcessorCount, 0);
    int n_tiles = (n_nodes + M_TILE - 1) / M_TILE;
    int grid = n_tiles < sms ? n_tiles : sms;
    mlp_kernel<<<grid, THREADS, SM_TOTAL>>>(h, W1, b1, W2, b2, out,
                                            n_nodes, n_tiles);
}